// round 11
// baseline (speedup 1.0000x reference)
#include <cuda_runtime.h>
#include <cstdint>
#include <cstddef>

#define B_   4
#define T_   1024
#define H_   32
#define KVH_ 8
#define HD_  128
#define DM_  4096
#define NTOK (B_ * T_)
#define KDIM 4096

// ---------------------------------------------------------------------------
// Scratch (device globals — no runtime allocation allowed)
// ---------------------------------------------------------------------------
__device__ float g_x  [(size_t)NTOK * DM_];    // rna(x)
__device__ float g_wqT [(size_t)DM_ * DM_];    // rna(w_q)^T  [N][K]
__device__ float g_wkvT[(size_t)2048 * DM_];   // rna(w_kv)^T [N][K]
__device__ float g_woT [(size_t)DM_ * DM_];    // rna(w_o)^T  [N][K]
__device__ float g_q  [(size_t)NTOK * DM_];    // q after proj+rope (rna)
__device__ float g_kv [(size_t)NTOK * 2048];   // [n][ k(8*128) | v(8*128) ] (rna)
__device__ float g_att[(size_t)NTOK * DM_];    // attention out (rna)

// ---------------------------------------------------------------------------
// helpers
// ---------------------------------------------------------------------------
__device__ __forceinline__ uint32_t f2tf(float x) {
    uint32_t r;
    asm("cvt.rna.tf32.f32 %0, %1;" : "=r"(r) : "f"(x));
    return r;
}

__device__ __forceinline__ uint32_t smem_u32(const void* p) {
    uint32_t a;
    asm("{ .reg .u64 t; cvta.to.shared.u64 t, %1; cvt.u32.u64 %0, t; }"
        : "=r"(a) : "l"(p));
    return a;
}

__device__ __forceinline__ void cp_async16(uint32_t dst, const float* src) {
    asm volatile("cp.async.cg.shared.global [%0], [%1], 16;\n"
                 :: "r"(dst), "l"(src) : "memory");
}
#define CP_COMMIT() asm volatile("cp.async.commit_group;\n" ::: "memory")
#define CP_WAIT(n)  asm volatile("cp.async.wait_group %0;\n" :: "n"(n) : "memory")

__device__ __forceinline__ void mma_tf32(float d[4], const uint32_t a[4],
                                         uint32_t b0, uint32_t b1) {
    asm volatile(
        "mma.sync.aligned.m16n8k8.row.col.f32.tf32.tf32.f32 "
        "{%0,%1,%2,%3}, {%4,%5,%6,%7}, {%8,%9}, {%0,%1,%2,%3};\n"
        : "+f"(d[0]), "+f"(d[1]), "+f"(d[2]), "+f"(d[3])
        : "r"(a[0]), "r"(a[1]), "r"(a[2]), "r"(a[3]), "r"(b0), "r"(b1));
}

// ---------------------------------------------------------------------------
// tf32 GEMM: C[M,N] = A[M,K] @ Bt[N,K]^T. A, Bt pre-rounded to tf32.
// Block 256x128, BK=64, 256 threads (8 warps, 4x2), warp tile 64x64.
// 2-stage cp.async double-buffer. smem tiles K-major [outer][68].
// Fused epilogue modes:
//   0: raw store                       (O-projection)
//   1: rope(all cols) + rna-round      (Q-projection)
//   2: rope(cols<1024) / rna(cols>=)   (KV-projection: K rope'd, V rounded)
// ---------------------------------------------------------------------------
#define BM 256
#define BN 128
#define BK 64
#define NST 2
#define TS 68                          // smem row stride (floats)
#define A_TILE_F (BM * TS)             // 17408 floats
#define B_TILE_F (BN * TS)             // 8704 floats
#define STG_F (A_TILE_F + B_TILE_F)    // 26112 floats = 104448 B
#define GEMM_SMEM (NST * STG_F * 4)    // 208896 B

__global__ void __launch_bounds__(256, 1)
gemm_tc(const float* __restrict__ A, const float* __restrict__ Bt,
        float* __restrict__ C, int N, int mode,
        const float* __restrict__ rcos, const float* __restrict__ rsin) {
    extern __shared__ float sm[];
    const uint32_t sbase = smem_u32(sm);

    const int tid  = threadIdx.x;
    const int warp = tid >> 5;
    const int lane = tid & 31;
    const int wm = warp & 3;           // M: 4 warps, 64 rows each
    const int wn = warp >> 2;          // N: 2 warps, 64 cols each
    const int gr = lane >> 2;
    const int tg = lane & 3;
    const int m0 = blockIdx.y * BM;
    const int n0 = blockIdx.x * BN;
    const int NK = KDIM / BK;          // 64 iterations

    const float* aseg = A  + (size_t)m0 * KDIM;
    const float* bseg = Bt + (size_t)n0 * KDIM;

    auto load_stage = [&](int s, int kt) {
        const uint32_t dst = sbase + (uint32_t)(s * STG_F) * 4u;
        const int kf = kt * BK;
        #pragma unroll
        for (int p = 0; p < 16; p++) {              // A: 4096 float4
            int i = tid + p * 256;
            int row = i >> 4, u = i & 15;
            cp_async16(dst + (uint32_t)(row * TS + u * 4) * 4u,
                       aseg + (size_t)row * KDIM + kf + u * 4);
        }
        const uint32_t dstB = dst + (uint32_t)A_TILE_F * 4u;
        #pragma unroll
        for (int p = 0; p < 8; p++) {               // B: 2048 float4
            int i = tid + p * 256;
            int row = i >> 4, u = i & 15;
            cp_async16(dstB + (uint32_t)(row * TS + u * 4) * 4u,
                       bseg + (size_t)row * KDIM + kf + u * 4);
        }
        CP_COMMIT();
    };

    float acc[4][8][4];
    #pragma unroll
    for (int mt = 0; mt < 4; mt++)
        #pragma unroll
        for (int nt = 0; nt < 8; nt++)
            #pragma unroll
            for (int e = 0; e < 4; e++) acc[mt][nt][e] = 0.f;

    load_stage(0, 0);

    for (int kt = 0; kt < NK; kt++) {
        if (kt + 1 < NK) {
            load_stage((kt + 1) & 1, kt + 1);  // prefetch next buffer
            CP_WAIT(1);                        // current stage landed
        } else {
            CP_WAIT(0);
        }
        __syncthreads();

        const float* As = sm + (size_t)(kt & 1) * STG_F;
        const float* Bs = As + A_TILE_F;
        const float* Aw = As + (wm * 64 + gr) * TS;
        const float* Bw = Bs + (wn * 64 + gr) * TS;

        #pragma unroll
        for (int ks = 0; ks < 8; ks++) {
            const int c0 = ks * 8 + tg;
            uint32_t af[4][4];
            #pragma unroll
            for (int mt = 0; mt < 4; mt++) {
                const float* ap = Aw + mt * 16 * TS;
                af[mt][0] = __float_as_uint(ap[c0]);
                af[mt][1] = __float_as_uint(ap[8 * TS + c0]);
                af[mt][2] = __float_as_uint(ap[c0 + 4]);
                af[mt][3] = __float_as_uint(ap[8 * TS + c0 + 4]);
            }
            #pragma unroll
            for (int nt = 0; nt < 8; nt++) {
                const float* bp = Bw + nt * 8 * TS;
                uint32_t b0 = __float_as_uint(bp[c0]);
                uint32_t b1 = __float_as_uint(bp[c0 + 4]);
                #pragma unroll
                for (int mt = 0; mt < 4; mt++)
                    mma_tf32(acc[mt][nt], af[mt], b0, b1);
            }
        }
        __syncthreads();   // compute done before next iter overwrites this buf
    }

    // ---- fused epilogue ----
    #pragma unroll
    for (int mt = 0; mt < 4; mt++) {
        #pragma unroll
        for (int e2 = 0; e2 < 2; e2++) {
            int row = m0 + wm * 64 + mt * 16 + gr + e2 * 8;
            float* crow = C + (size_t)row * N + n0 + wn * 64;
            if (mode == 0) {
                #pragma unroll
                for (int nt = 0; nt < 8; nt++) {
                    float2 v;
                    v.x = acc[mt][nt][e2 * 2];
                    v.y = acc[mt][nt][e2 * 2 + 1];
                    *(float2*)(crow + nt * 8 + 2 * tg) = v;
                }
            } else {
                int pos = row & (T_ - 1);
                #pragma unroll
                for (int nt = 0; nt < 8; nt++) {
                    float x1 = acc[mt][nt][e2 * 2];
                    float x2 = acc[mt][nt][e2 * 2 + 1];
                    int col = n0 + wn * 64 + nt * 8 + 2 * tg;  // even element col
                    float2 v;
                    if (mode == 1 || col < 1024) {
                        int i = (col & 127) >> 1;              // rope pair idx
                        float cs = __ldg(&rcos[pos * 64 + i]);
                        float sn = __ldg(&rsin[pos * 64 + i]);
                        v.x = __uint_as_float(f2tf(x1 * cs - x2 * sn));
                        v.y = __uint_as_float(f2tf(x1 * sn + x2 * cs));
                    } else {
                        v.x = __uint_as_float(f2tf(x1));
                        v.y = __uint_as_float(f2tf(x2));
                    }
                    *(float2*)(crow + nt * 8 + 2 * tg) = v;
                }
            }
        }
    }
}

// ---------------------------------------------------------------------------
// prep kernels
// ---------------------------------------------------------------------------
__global__ void round_x_kernel(const float* __restrict__ in, float* __restrict__ out,
                               int n4) {
    int i = blockIdx.x * blockDim.x + threadIdx.x;
    if (i >= n4) return;
    float4 v = ((const float4*)in)[i];
    v.x = __uint_as_float(f2tf(v.x));
    v.y = __uint_as_float(f2tf(v.y));
    v.z = __uint_as_float(f2tf(v.z));
    v.w = __uint_as_float(f2tf(v.w));
    ((float4*)out)[i] = v;
}

__global__ void transpose_rna_kernel(const float* __restrict__ W, float* __restrict__ Wt,
                                     int rows /*K*/, int cols /*N*/) {
    __shared__ float t[32][33];
    int bx = blockIdx.x * 32;
    int by = blockIdx.y * 32;
    int lx = threadIdx.x, ly = threadIdx.y;   // 32 x 8
    #pragma unroll
    for (int i = 0; i < 32; i += 8)
        t[ly + i][lx] = W[(size_t)(by + ly + i) * cols + bx + lx];
    __syncthreads();
    #pragma unroll
    for (int i = 0; i < 32; i += 8)
        Wt[(size_t)(bx + ly + i) * rows + by + lx] =
            __uint_as_float(f2tf(t[lx][ly + i]));
}

// ---------------------------------------------------------------------------
// Flash attention, causal, GQA, tf32 mma. All inputs pre-rounded to tf32.
// grid = (T/64, H, nb), block = 128 (4 warps). b = b_off + blockIdx.z.
// Longest causal tiles scheduled first. smem 101KB -> 2 CTAs/SM.
// ---------------------------------------------------------------------------
#define ATT_SMEM_FLOATS (3 * 64 * 132)

__global__ void __launch_bounds__(128)
attn_kernel(const float* __restrict__ q, const float* __restrict__ kv,
            float* __restrict__ out, int b_off) {
    extern __shared__ float sm[];
    float* Ks = sm;
    float* Vs = sm + 64 * 132;
    float* Qs = sm + 2 * 64 * 132;
    float* Ps = Qs;                    // alias: safe (per-warp rows)
    const uint32_t sK = smem_u32(Ks);
    const uint32_t sV = smem_u32(Vs);

    const int mblk = gridDim.x - 1 - blockIdx.x;   // longest tiles first
    const int m0  = mblk * 64;
    const int h   = blockIdx.y;
    const int b   = b_off + blockIdx.z;
    const int kvh = h >> 2;
    const int tid  = threadIdx.x;
    const int warp = tid >> 5;
    const int lane = tid & 31;
    const int gr = lane >> 2;
    const int tg = lane & 3;

    for (int i = tid; i < 64 * 32; i += 128) {
        int r = i >> 5, c4 = i & 31;
        float4 v = *(const float4*)&q[((size_t)(b * T_ + m0 + r) * H_ + h) * HD_ + c4 * 4];
        *(float4*)&Qs[r * 132 + c4 * 4] = v;
    }
    __syncthreads();

    uint32_t qf[16][4];
    #pragma unroll
    for (int ks = 0; ks < 16; ks++) {
        int r0 = warp * 16 + gr;
        int c0 = ks * 8 + tg;
        qf[ks][0] = __float_as_uint(Qs[r0 * 132 + c0]);
        qf[ks][1] = __float_as_uint(Qs[(r0 + 8) * 132 + c0]);
        qf[ks][2] = __float_as_uint(Qs[r0 * 132 + c0 + 4]);
        qf[ks][3] = __float_as_uint(Qs[(r0 + 8) * 132 + c0 + 4]);
    }

    float o_acc[16][4];
    #pragma unroll
    for (int nt = 0; nt < 16; nt++)
        #pragma unroll
        for (int e = 0; e < 4; e++) o_acc[nt][e] = 0.f;
    float m_i[2] = {-INFINITY, -INFINITY};
    float l_i[2] = {0.f, 0.f};

    const float scale = 0.08838834764831845f;
    const int ktiles = m0 / 64 + 1;

    for (int kt = 0; kt < ktiles; kt++) {
        int k0 = kt * 64;
        __syncthreads();
        {
            const float* base = &kv[(size_t)(b * T_ + k0) * 2048 + kvh * 128];
            #pragma unroll
            for (int p = 0; p < 16; p++) {
                int i = tid + p * 128;
                int r = i >> 5, c4 = i & 31;
                uint32_t soff = (uint32_t)(r * 132 + c4 * 4) * 4u;
                const float* kp = base + (size_t)r * 2048;
                cp_async16(sK + soff, kp + c4 * 4);
                cp_async16(sV + soff, kp + 1024 + c4 * 4);
            }
            CP_COMMIT();
            CP_WAIT(0);
        }
        __syncthreads();

        float s[8][4];
        #pragma unroll
        for (int nt = 0; nt < 8; nt++)
            #pragma unroll
            for (int e = 0; e < 4; e++) s[nt][e] = 0.f;

        #pragma unroll 4
        for (int ks = 0; ks < 16; ks++) {
            #pragma unroll
            for (int nt = 0; nt < 8; nt++) {
                int cc = nt * 8 + gr;
                int rr = ks * 8 + tg;
                uint32_t b0 = __float_as_uint(Ks[cc * 132 + rr]);
                uint32_t b1 = __float_as_uint(Ks[cc * 132 + rr + 4]);
                mma_tf32(s[nt], qf[ks], b0, b1);
            }
        }

        bool diag = (kt == ktiles - 1);
        #pragma unroll
        for (int nt = 0; nt < 8; nt++)
            #pragma unroll
            for (int e = 0; e < 4; e++) {
                int row = warp * 16 + gr + ((e >= 2) ? 8 : 0);
                int col = nt * 8 + 2 * tg + (e & 1);
                float v = s[nt][e] * scale;
                if (diag && (k0 + col > m0 + row)) v = -1e9f;
                s[nt][e] = v;
            }

        #pragma unroll
        for (int half = 0; half < 2; half++) {
            float mx = -INFINITY;
            #pragma unroll
            for (int nt = 0; nt < 8; nt++) {
                mx = fmaxf(mx, s[nt][half * 2]);
                mx = fmaxf(mx, s[nt][half * 2 + 1]);
            }
            mx = fmaxf(mx, __shfl_xor_sync(0xffffffffu, mx, 1));
            mx = fmaxf(mx, __shfl_xor_sync(0xffffffffu, mx, 2));
            float mnew = fmaxf(m_i[half], mx);
            float corr = __expf(m_i[half] - mnew);
            float lsum = 0.f;
            #pragma unroll
            for (int nt = 0; nt < 8; nt++) {
                float e0 = __expf(s[nt][half * 2]     - mnew);
                float e1 = __expf(s[nt][half * 2 + 1] - mnew);
                s[nt][half * 2]     = e0;
                s[nt][half * 2 + 1] = e1;
                lsum += e0 + e1;
            }
            lsum += __shfl_xor_sync(0xffffffffu, lsum, 1);
            lsum += __shfl_xor_sync(0xffffffffu, lsum, 2);
            m_i[half] = mnew;
            l_i[half] = l_i[half] * corr + lsum;
            #pragma unroll
            for (int nt = 0; nt < 16; nt++) {
                o_acc[nt][half * 2]     *= corr;
                o_acc[nt][half * 2 + 1] *= corr;
            }
        }

        #pragma unroll
        for (int nt = 0; nt < 8; nt++)
            #pragma unroll
            for (int e = 0; e < 4; e++) {
                int row = warp * 16 + gr + ((e >= 2) ? 8 : 0);
                int col = nt * 8 + 2 * tg + (e & 1);
                Ps[row * 132 + col] = __uint_as_float(f2tf(s[nt][e]));
            }
        __syncwarp();

        #pragma unroll
        for (int ks = 0; ks < 8; ks++) {
            uint32_t pa[4];
            int r0 = warp * 16 + gr;
            int c0 = ks * 8 + tg;
            pa[0] = __float_as_uint(Ps[r0 * 132 + c0]);
            pa[1] = __float_as_uint(Ps[(r0 + 8) * 132 + c0]);
            pa[2] = __float_as_uint(Ps[r0 * 132 + c0 + 4]);
            pa[3] = __float_as_uint(Ps[(r0 + 8) * 132 + c0 + 4]);
            #pragma unroll
            for (int nt = 0; nt < 16; nt++) {
                uint32_t b0 = __float_as_uint(Vs[(ks * 8 + tg) * 132 + nt * 8 + gr]);
                uint32_t b1 = __float_as_uint(Vs[(ks * 8 + tg + 4) * 132 + nt * 8 + gr]);
                mma_tf32(o_acc[nt], pa, b0, b1);
            }
        }
    }

    #pragma unroll
    for (int nt = 0; nt < 16; nt++)
        #pragma unroll
        for (int e = 0; e < 4; e++) {
            int row = warp * 16 + gr + ((e >= 2) ? 8 : 0);
            int col = nt * 8 + 2 * tg + (e & 1);
            float inv_l = 1.f / l_i[(e >= 2) ? 1 : 0];
            out[((size_t)(b * T_ + m0 + row) * H_ + h) * HD_ + col] =
                __uint_as_float(f2tf(o_acc[nt][e] * inv_l));
        }
}

// ---------------------------------------------------------------------------
// launch — fork (Q chain ∥ KV chain), rope fused in gemm epilogues,
// then attn/O-GEMM split pipeline
// ---------------------------------------------------------------------------
extern "C" void kernel_launch(void* const* d_in, const int* in_sizes, int n_in,
                              void* d_out, int out_size) {
    const float* x    = (const float*)d_in[0];
    const float* w_q  = (const float*)d_in[1];
    const float* w_kv = (const float*)d_in[2];
    const float* w_o  = (const float*)d_in[3];
    const float* rcos = (const float*)d_in[6];
    const float* rsin = (const float*)d_in[7];
    float* out = (float*)d_out;

    float *xb, *wqT, *wkvT, *woT, *qb, *kvb, *ab;
    cudaGetSymbolAddress((void**)&xb,   g_x);
    cudaGetSymbolAddress((void**)&wqT,  g_wqT);
    cudaGetSymbolAddress((void**)&wkvT, g_wkvT);
    cudaGetSymbolAddress((void**)&woT,  g_woT);
    cudaGetSymbolAddress((void**)&qb,   g_q);
    cudaGetSymbolAddress((void**)&kvb,  g_kv);
    cudaGetSymbolAddress((void**)&ab,   g_att);

    static cudaStream_t s1 = nullptr;
    static cudaEvent_t ev_start = nullptr, ev_rx = nullptr, ev_q = nullptr,
                       ev_wo = nullptr, ev_a0 = nullptr, ev_o0 = nullptr;
    if (s1 == nullptr) {
        cudaStreamCreateWithFlags(&s1, cudaStreamNonBlocking);
        cudaEventCreateWithFlags(&ev_start, cudaEventDisableTiming);
        cudaEventCreateWithFlags(&ev_rx,    cudaEventDisableTiming);
        cudaEventCreateWithFlags(&ev_q,     cudaEventDisableTiming);
        cudaEventCreateWithFlags(&ev_wo,    cudaEventDisableTiming);
        cudaEventCreateWithFlags(&ev_a0,    cudaEventDisableTiming);
        cudaEventCreateWithFlags(&ev_o0,    cudaEventDisableTiming);
        cudaFuncSetAttribute(gemm_tc,
            cudaFuncAttributeMaxDynamicSharedMemorySize, GEMM_SMEM);
        cudaFuncSetAttribute(attn_kernel,
            cudaFuncAttributeMaxDynamicSharedMemorySize, ATT_SMEM_FLOATS * 4);
    }

    // fork
    cudaEventRecord(ev_start, 0);
    cudaStreamWaitEvent(s1, ev_start, 0);

    // s0: round x, then KV chain (rope+round fused into gemm epilogue)
    round_x_kernel<<<(NTOK * DM_ / 4 + 255) / 256, 256>>>(x, xb, NTOK * DM_ / 4);
    cudaEventRecord(ev_rx, 0);
    transpose_rna_kernel<<<dim3(2048 / 32, DM_ / 32), dim3(32, 8)>>>(w_kv, wkvT, DM_, 2048);
    gemm_tc<<<dim3(2048 / BN, NTOK / BM), 256, GEMM_SMEM>>>(
        xb, wkvT, kvb, 2048, 2, rcos, rsin);

    // s1: Q chain (concurrent with KV chain) + w_o transpose
    transpose_rna_kernel<<<dim3(DM_ / 32, DM_ / 32), dim3(32, 8), 0, s1>>>(w_q, wqT, DM_, DM_);
    cudaStreamWaitEvent(s1, ev_rx, 0);
    gemm_tc<<<dim3(DM_ / BN, NTOK / BM), 256, GEMM_SMEM, s1>>>(
        xb, wqT, qb, DM_, 1, rcos, rsin);
    cudaEventRecord(ev_q, s1);
    transpose_rna_kernel<<<dim3(DM_ / 32, DM_ / 32), dim3(32, 8), 0, s1>>>(w_o, woT, DM_, DM_);
    cudaEventRecord(ev_wo, s1);

    // s0: attention half 0 (batches 0,1), then half 1 (batches 2,3)
    cudaStreamWaitEvent(0, ev_q, 0);
    attn_kernel<<<dim3(T_ / 64, H_, 2), 128, ATT_SMEM_FLOATS * 4>>>(qb, kvb, ab, 0);
    cudaEventRecord(ev_a0, 0);
    attn_kernel<<<dim3(T_ / 64, H_, 2), 128, ATT_SMEM_FLOATS * 4>>>(qb, kvb, ab, 2);

    // s1: O-projection half 0 (rows 0..2047) overlapping attention half 1
    cudaStreamWaitEvent(s1, ev_a0, 0);
    cudaStreamWaitEvent(s1, ev_wo, 0);
    gemm_tc<<<dim3(DM_ / BN, (NTOK / 2) / BM), 256, GEMM_SMEM, s1>>>(
        ab, woT, out, DM_, 0, rcos, rsin);
    cudaEventRecord(ev_o0, s1);

    // s0: O-projection half 1 (rows 2048..4095), then join
    cudaStreamWaitEvent(0, ev_wo, 0);
    gemm_tc<<<dim3(DM_ / BN, (NTOK / 2) / BM), 256, GEMM_SMEM>>>(
        ab + (size_t)(NTOK / 2) * DM_, woT, out + (size_t)(NTOK / 2) * DM_,
        DM_, 0, rcos, rsin);
    cudaStreamWaitEvent(0, ev_o0, 0);
}

// round 13
// speedup vs baseline: 1.6096x; 1.6096x over previous
#include <cuda_runtime.h>
#include <cuda_fp16.h>
#include <cstdint>
#include <cstddef>

#define B_   4
#define T_   1024
#define H_   32
#define KVH_ 8
#define HD_  128
#define DM_  4096
#define NTOK (B_ * T_)
#define KDIM 4096

// ---------------------------------------------------------------------------
// Scratch (device globals — no runtime allocation allowed)
// ---------------------------------------------------------------------------
__device__ __half g_xh  [(size_t)NTOK * DM_];   // fp16(x)
__device__ __half g_wqTh [(size_t)DM_ * DM_];   // fp16(w_q)^T  [N][K]
__device__ __half g_wkvTh[(size_t)2048 * DM_];  // fp16(w_kv)^T [N][K]
__device__ __half g_woTh [(size_t)DM_ * DM_];   // fp16(w_o)^T  [N][K]
__device__ float  g_q  [(size_t)NTOK * DM_];    // q after proj+rope (tf32-rounded fp32)
__device__ float  g_kv [(size_t)NTOK * 2048];   // [n][ k(8*128) | v(8*128) ]
__device__ __half g_atth[(size_t)NTOK * DM_];   // attention out (fp16)

// ---------------------------------------------------------------------------
// helpers
// ---------------------------------------------------------------------------
__device__ __forceinline__ uint32_t f2tf(float x) {
    uint32_t r;
    asm("cvt.rna.tf32.f32 %0, %1;" : "=r"(r) : "f"(x));
    return r;
}

__device__ __forceinline__ uint32_t smem_u32(const void* p) {
    uint32_t a;
    asm("{ .reg .u64 t; cvta.to.shared.u64 t, %1; cvt.u32.u64 %0, t; }"
        : "=r"(a) : "l"(p));
    return a;
}

__device__ __forceinline__ void cp_async16(uint32_t dst, const void* src) {
    asm volatile("cp.async.cg.shared.global [%0], [%1], 16;\n"
                 :: "r"(dst), "l"(src) : "memory");
}
#define CP_COMMIT() asm volatile("cp.async.commit_group;\n" ::: "memory")
#define CP_WAIT(n)  asm volatile("cp.async.wait_group %0;\n" :: "n"(n) : "memory")

// tf32 mma (attention)
__device__ __forceinline__ void mma_tf32(float d[4], const uint32_t a[4],
                                         uint32_t b0, uint32_t b1) {
    asm volatile(
        "mma.sync.aligned.m16n8k8.row.col.f32.tf32.tf32.f32 "
        "{%0,%1,%2,%3}, {%4,%5,%6,%7}, {%8,%9}, {%0,%1,%2,%3};\n"
        : "+f"(d[0]), "+f"(d[1]), "+f"(d[2]), "+f"(d[3])
        : "r"(a[0]), "r"(a[1]), "r"(a[2]), "r"(a[3]), "r"(b0), "r"(b1));
}

// fp16 mma (projection GEMMs): 2048 MAC/instr
__device__ __forceinline__ void mma_f16(float d[4], const uint32_t a[4],
                                        uint32_t b0, uint32_t b1) {
    asm volatile(
        "mma.sync.aligned.m16n8k16.row.col.f32.f16.f16.f32 "
        "{%0,%1,%2,%3}, {%4,%5,%6,%7}, {%8,%9}, {%0,%1,%2,%3};\n"
        : "+f"(d[0]), "+f"(d[1]), "+f"(d[2]), "+f"(d[3])
        : "r"(a[0]), "r"(a[1]), "r"(a[2]), "r"(a[3]), "r"(b0), "r"(b1));
}

// ---------------------------------------------------------------------------
// fp16 GEMM: C[M,N](fp32) = A[M,K](fp16) @ Bt[N,K](fp16)^T.
// Block 256x128, BK=64, 256 threads (8 warps, 4x2), warp tile 64x64.
// 2-stage cp.async double-buffer. smem tiles K-major [outer][72] halves.
// Fused epilogue modes:
//   0: raw fp32 store                  (O-projection -> out)
//   1: rope(all cols) + tf32-round     (Q-projection -> g_q)
//   2: rope(cols<1024) / tf32 round    (KV-projection -> g_kv)
// ---------------------------------------------------------------------------
#define BM 256
#define BN 128
#define BK 64
#define HTS 72                          // smem row stride (halves)
#define A_TILE_B (BM * HTS * 2)         // 36864 bytes
#define B_TILE_B (BN * HTS * 2)         // 18432 bytes
#define STG_B (A_TILE_B + B_TILE_B)     // 55296 bytes
#define GEMM_SMEM (2 * STG_B)           // 110592 bytes

__global__ void __launch_bounds__(256, 1)
gemm_tc(const __half* __restrict__ A, const __half* __restrict__ Bt,
        float* __restrict__ C, int N, int mode,
        const float* __restrict__ rcos, const float* __restrict__ rsin) {
    extern __shared__ char smc[];
    const uint32_t sbase = smem_u32(smc);

    const int tid  = threadIdx.x;
    const int warp = tid >> 5;
    const int lane = tid & 31;
    const int wm = warp & 3;           // M: 4 warps, 64 rows each
    const int wn = warp >> 2;          // N: 2 warps, 64 cols each
    const int gr = lane >> 2;
    const int tg = lane & 3;
    const int m0 = blockIdx.y * BM;
    const int n0 = blockIdx.x * BN;
    const int NK = KDIM / BK;          // 64 iterations

    const __half* aseg = A  + (size_t)m0 * KDIM;
    const __half* bseg = Bt + (size_t)n0 * KDIM;

    auto load_stage = [&](int s, int kt) {
        const uint32_t dst = sbase + (uint32_t)s * STG_B;
        const int kf = kt * BK;        // half index
        #pragma unroll
        for (int p = 0; p < 8; p++) {               // A: 2048 x 16B chunks
            int i = tid + p * 256;
            int row = i >> 3, u = i & 7;
            cp_async16(dst + (uint32_t)(row * 144 + u * 16),
                       aseg + (size_t)row * KDIM + kf + u * 8);
        }
        const uint32_t dstB = dst + (uint32_t)A_TILE_B;
        #pragma unroll
        for (int p = 0; p < 4; p++) {               // B: 1024 x 16B chunks
            int i = tid + p * 256;
            int row = i >> 3, u = i & 7;
            cp_async16(dstB + (uint32_t)(row * 144 + u * 16),
                       bseg + (size_t)row * KDIM + kf + u * 8);
        }
        CP_COMMIT();
    };

    float acc[4][8][4];
    #pragma unroll
    for (int mt = 0; mt < 4; mt++)
        #pragma unroll
        for (int nt = 0; nt < 8; nt++)
            #pragma unroll
            for (int e = 0; e < 4; e++) acc[mt][nt][e] = 0.f;

    load_stage(0, 0);

    for (int kt = 0; kt < NK; kt++) {
        if (kt + 1 < NK) {
            load_stage((kt + 1) & 1, kt + 1);  // prefetch next buffer
            CP_WAIT(1);                        // current stage landed
        } else {
            CP_WAIT(0);
        }
        __syncthreads();

        const __half* As = (const __half*)(smc + (size_t)(kt & 1) * STG_B);
        const __half* Bs = (const __half*)((const char*)As + A_TILE_B);
        const __half* Aw = As + (wm * 64 + gr) * HTS;
        const __half* Bw = Bs + (wn * 64 + gr) * HTS;

        #pragma unroll
        for (int ks = 0; ks < 4; ks++) {           // 4 x k16 steps
            const int c0 = ks * 16 + 2 * tg;       // half index of k-pair
            uint32_t af[4][4];
            #pragma unroll
            for (int mt = 0; mt < 4; mt++) {
                const __half* ap = Aw + mt * 16 * HTS;
                af[mt][0] = *(const uint32_t*)(ap + c0);
                af[mt][1] = *(const uint32_t*)(ap + 8 * HTS + c0);
                af[mt][2] = *(const uint32_t*)(ap + c0 + 8);
                af[mt][3] = *(const uint32_t*)(ap + 8 * HTS + c0 + 8);
            }
            #pragma unroll
            for (int nt = 0; nt < 8; nt++) {
                const __half* bp = Bw + nt * 8 * HTS;
                uint32_t b0 = *(const uint32_t*)(bp + c0);
                uint32_t b1 = *(const uint32_t*)(bp + c0 + 8);
                #pragma unroll
                for (int mt = 0; mt < 4; mt++)
                    mma_f16(acc[mt][nt], af[mt], b0, b1);
            }
        }
        __syncthreads();   // compute done before next iter overwrites this buf
    }

    // ---- fused epilogue (fp32 out) ----
    #pragma unroll
    for (int mt = 0; mt < 4; mt++) {
        #pragma unroll
        for (int e2 = 0; e2 < 2; e2++) {
            int row = m0 + wm * 64 + mt * 16 + gr + e2 * 8;
            float* crow = C + (size_t)row * N + n0 + wn * 64;
            if (mode == 0) {
                #pragma unroll
                for (int nt = 0; nt < 8; nt++) {
                    float2 v;
                    v.x = acc[mt][nt][e2 * 2];
                    v.y = acc[mt][nt][e2 * 2 + 1];
                    *(float2*)(crow + nt * 8 + 2 * tg) = v;
                }
            } else {
                int pos = row & (T_ - 1);
                #pragma unroll
                for (int nt = 0; nt < 8; nt++) {
                    float x1 = acc[mt][nt][e2 * 2];
                    float x2 = acc[mt][nt][e2 * 2 + 1];
                    int col = n0 + wn * 64 + nt * 8 + 2 * tg;  // even col
                    float2 v;
                    if (mode == 1 || col < 1024) {
                        int i = (col & 127) >> 1;              // rope pair idx
                        float cs = __ldg(&rcos[pos * 64 + i]);
                        float sn = __ldg(&rsin[pos * 64 + i]);
                        v.x = __uint_as_float(f2tf(x1 * cs - x2 * sn));
                        v.y = __uint_as_float(f2tf(x1 * sn + x2 * cs));
                    } else {
                        v.x = __uint_as_float(f2tf(x1));
                        v.y = __uint_as_float(f2tf(x2));
                    }
                    *(float2*)(crow + nt * 8 + 2 * tg) = v;
                }
            }
        }
    }
}

// ---------------------------------------------------------------------------
// prep kernels: fp32 -> fp16
// ---------------------------------------------------------------------------
__global__ void round_x_h(const float* __restrict__ in, __half* __restrict__ out,
                          int n4) {
    int i = blockIdx.x * blockDim.x + threadIdx.x;
    if (i >= n4) return;
    float4 v = ((const float4*)in)[i];
    __half2 h0 = __floats2half2_rn(v.x, v.y);
    __half2 h1 = __floats2half2_rn(v.z, v.w);
    ((__half2*)out)[2 * i]     = h0;
    ((__half2*)out)[2 * i + 1] = h1;
}

__global__ void transpose_h_kernel(const float* __restrict__ W, __half* __restrict__ Wt,
                                   int rows /*K*/, int cols /*N*/) {
    __shared__ float t[32][33];
    int bx = blockIdx.x * 32;
    int by = blockIdx.y * 32;
    int lx = threadIdx.x, ly = threadIdx.y;   // 32 x 8
    #pragma unroll
    for (int i = 0; i < 32; i += 8)
        t[ly + i][lx] = W[(size_t)(by + ly + i) * cols + bx + lx];
    __syncthreads();
    #pragma unroll
    for (int i = 0; i < 32; i += 8)
        Wt[(size_t)(bx + ly + i) * rows + by + lx] = __float2half_rn(t[lx][ly + i]);
}

// ---------------------------------------------------------------------------
// Flash attention, causal, GQA, tf32 mma. Inputs fp32 (tf32-rounded).
// Output: fp16 (feeds O-projection's fp16 A operand).
// grid = (T/64, H, nb), block = 128 (4 warps). b = b_off + blockIdx.z.
// ---------------------------------------------------------------------------
#define ATT_SMEM_FLOATS (3 * 64 * 132)

__global__ void __launch_bounds__(128)
attn_kernel(const float* __restrict__ q, const float* __restrict__ kv,
            __half* __restrict__ out, int b_off) {
    extern __shared__ float sm[];
    float* Ks = sm;
    float* Vs = sm + 64 * 132;
    float* Qs = sm + 2 * 64 * 132;
    float* Ps = Qs;                    // alias: safe (per-warp rows)
    const uint32_t sK = smem_u32(Ks);
    const uint32_t sV = smem_u32(Vs);

    const int mblk = gridDim.x - 1 - blockIdx.x;   // longest tiles first
    const int m0  = mblk * 64;
    const int h   = blockIdx.y;
    const int b   = b_off + blockIdx.z;
    const int kvh = h >> 2;
    const int tid  = threadIdx.x;
    const int warp = tid >> 5;
    const int lane = tid & 31;
    const int gr = lane >> 2;
    const int tg = lane & 3;

    for (int i = tid; i < 64 * 32; i += 128) {
        int r = i >> 5, c4 = i & 31;
        float4 v = *(const float4*)&q[((size_t)(b * T_ + m0 + r) * H_ + h) * HD_ + c4 * 4];
        *(float4*)&Qs[r * 132 + c4 * 4] = v;
    }
    __syncthreads();

    uint32_t qf[16][4];
    #pragma unroll
    for (int ks = 0; ks < 16; ks++) {
        int r0 = warp * 16 + gr;
        int c0 = ks * 8 + tg;
        qf[ks][0] = __float_as_uint(Qs[r0 * 132 + c0]);
        qf[ks][1] = __float_as_uint(Qs[(r0 + 8) * 132 + c0]);
        qf[ks][2] = __float_as_uint(Qs[r0 * 132 + c0 + 4]);
        qf[ks][3] = __float_as_uint(Qs[(r0 + 8) * 132 + c0 + 4]);
    }

    float o_acc[16][4];
    #pragma unroll
    for (int nt = 0; nt < 16; nt++)
        #pragma unroll
        for (int e = 0; e < 4; e++) o_acc[nt][e] = 0.f;
    float m_i[2] = {-INFINITY, -INFINITY};
    float l_i[2] = {0.f, 0.f};

    const float scale = 0.08838834764831845f;
    const int ktiles = m0 / 64 + 1;

    for (int kt = 0; kt < ktiles; kt++) {
        int k0 = kt * 64;
        __syncthreads();
        {
            const float* base = &kv[(size_t)(b * T_ + k0) * 2048 + kvh * 128];
            #pragma unroll
            for (int p = 0; p < 16; p++) {
                int i = tid + p * 128;
                int r = i >> 5, c4 = i & 31;
                uint32_t soff = (uint32_t)(r * 132 + c4 * 4) * 4u;
                const float* kp = base + (size_t)r * 2048;
                cp_async16(sK + soff, kp + c4 * 4);
                cp_async16(sV + soff, kp + 1024 + c4 * 4);
            }
            CP_COMMIT();
            CP_WAIT(0);
        }
        __syncthreads();

        float s[8][4];
        #pragma unroll
        for (int nt = 0; nt < 8; nt++)
            #pragma unroll
            for (int e = 0; e < 4; e++) s[nt][e] = 0.f;

        #pragma unroll 4
        for (int ks = 0; ks < 16; ks++) {
            #pragma unroll
            for (int nt = 0; nt < 8; nt++) {
                int cc = nt * 8 + gr;
                int rr = ks * 8 + tg;
                uint32_t b0 = __float_as_uint(Ks[cc * 132 + rr]);
                uint32_t b1 = __float_as_uint(Ks[cc * 132 + rr + 4]);
                mma_tf32(s[nt], qf[ks], b0, b1);
            }
        }

        bool diag = (kt == ktiles - 1);
        #pragma unroll
        for (int nt = 0; nt < 8; nt++)
            #pragma unroll
            for (int e = 0; e < 4; e++) {
                int row = warp * 16 + gr + ((e >= 2) ? 8 : 0);
                int col = nt * 8 + 2 * tg + (e & 1);
                float v = s[nt][e] * scale;
                if (diag && (k0 + col > m0 + row)) v = -1e9f;
                s[nt][e] = v;
            }

        #pragma unroll
        for (int half = 0; half < 2; half++) {
            float mx = -INFINITY;
            #pragma unroll
            for (int nt = 0; nt < 8; nt++) {
                mx = fmaxf(mx, s[nt][half * 2]);
                mx = fmaxf(mx, s[nt][half * 2 + 1]);
            }
            mx = fmaxf(mx, __shfl_xor_sync(0xffffffffu, mx, 1));
            mx = fmaxf(mx, __shfl_xor_sync(0xffffffffu, mx, 2));
            float mnew = fmaxf(m_i[half], mx);
            float corr = __expf(m_i[half] - mnew);
            float lsum = 0.f;
            #pragma unroll
            for (int nt = 0; nt < 8; nt++) {
                float e0 = __expf(s[nt][half * 2]     - mnew);
                float e1 = __expf(s[nt][half * 2 + 1] - mnew);
                s[nt][half * 2]     = e0;
                s[nt][half * 2 + 1] = e1;
                lsum += e0 + e1;
            }
            lsum += __shfl_xor_sync(0xffffffffu, lsum, 1);
            lsum += __shfl_xor_sync(0xffffffffu, lsum, 2);
            m_i[half] = mnew;
            l_i[half] = l_i[half] * corr + lsum;
            #pragma unroll
            for (int nt = 0; nt < 16; nt++) {
                o_acc[nt][half * 2]     *= corr;
                o_acc[nt][half * 2 + 1] *= corr;
            }
        }

        #pragma unroll
        for (int nt = 0; nt < 8; nt++)
            #pragma unroll
            for (int e = 0; e < 4; e++) {
                int row = warp * 16 + gr + ((e >= 2) ? 8 : 0);
                int col = nt * 8 + 2 * tg + (e & 1);
                Ps[row * 132 + col] = __uint_as_float(f2tf(s[nt][e]));
            }
        __syncwarp();

        #pragma unroll
        for (int ks = 0; ks < 8; ks++) {
            uint32_t pa[4];
            int r0 = warp * 16 + gr;
            int c0 = ks * 8 + tg;
            pa[0] = __float_as_uint(Ps[r0 * 132 + c0]);
            pa[1] = __float_as_uint(Ps[(r0 + 8) * 132 + c0]);
            pa[2] = __float_as_uint(Ps[r0 * 132 + c0 + 4]);
            pa[3] = __float_as_uint(Ps[(r0 + 8) * 132 + c0 + 4]);
            #pragma unroll
            for (int nt = 0; nt < 16; nt++) {
                uint32_t b0 = __float_as_uint(Vs[(ks * 8 + tg) * 132 + nt * 8 + gr]);
                uint32_t b1 = __float_as_uint(Vs[(ks * 8 + tg + 4) * 132 + nt * 8 + gr]);
                mma_tf32(o_acc[nt], pa, b0, b1);
            }
        }
    }

    // epilogue: fp16 store (feeds fp16 O-projection)
    #pragma unroll
    for (int nt = 0; nt < 16; nt++)
        #pragma unroll
        for (int e = 0; e < 4; e++) {
            int row = warp * 16 + gr + ((e >= 2) ? 8 : 0);
            int col = nt * 8 + 2 * tg + (e & 1);
            float inv_l = 1.f / l_i[(e >= 2) ? 1 : 0];
            out[((size_t)(b * T_ + m0 + row) * H_ + h) * HD_ + col] =
                __float2half_rn(o_acc[nt][e] * inv_l);
        }
}

// ---------------------------------------------------------------------------
// launch — fork (Q chain ∥ KV chain), rope fused in gemm epilogues,
// then attn/O-GEMM split pipeline
// ---------------------------------------------------------------------------
extern "C" void kernel_launch(void* const* d_in, const int* in_sizes, int n_in,
                              void* d_out, int out_size) {
    const float* x    = (const float*)d_in[0];
    const float* w_q  = (const float*)d_in[1];
    const float* w_kv = (const float*)d_in[2];
    const float* w_o  = (const float*)d_in[3];
    const float* rcos = (const float*)d_in[6];
    const float* rsin = (const float*)d_in[7];
    float* out = (float*)d_out;

    __half *xh, *wqTh, *wkvTh, *woTh, *ath;
    float *qb, *kvb;
    cudaGetSymbolAddress((void**)&xh,    g_xh);
    cudaGetSymbolAddress((void**)&wqTh,  g_wqTh);
    cudaGetSymbolAddress((void**)&wkvTh, g_wkvTh);
    cudaGetSymbolAddress((void**)&woTh,  g_woTh);
    cudaGetSymbolAddress((void**)&qb,    g_q);
    cudaGetSymbolAddress((void**)&kvb,   g_kv);
    cudaGetSymbolAddress((void**)&ath,   g_atth);

    static cudaStream_t s1 = nullptr;
    static cudaEvent_t ev_start = nullptr, ev_rx = nullptr, ev_q = nullptr,
                       ev_wo = nullptr, ev_a0 = nullptr, ev_o0 = nullptr;
    if (s1 == nullptr) {
        cudaStreamCreateWithFlags(&s1, cudaStreamNonBlocking);
        cudaEventCreateWithFlags(&ev_start, cudaEventDisableTiming);
        cudaEventCreateWithFlags(&ev_rx,    cudaEventDisableTiming);
        cudaEventCreateWithFlags(&ev_q,     cudaEventDisableTiming);
        cudaEventCreateWithFlags(&ev_wo,    cudaEventDisableTiming);
        cudaEventCreateWithFlags(&ev_a0,    cudaEventDisableTiming);
        cudaEventCreateWithFlags(&ev_o0,    cudaEventDisableTiming);
        cudaFuncSetAttribute(gemm_tc,
            cudaFuncAttributeMaxDynamicSharedMemorySize, GEMM_SMEM);
        cudaFuncSetAttribute(attn_kernel,
            cudaFuncAttributeMaxDynamicSharedMemorySize, ATT_SMEM_FLOATS * 4);
    }

    // fork
    cudaEventRecord(ev_start, 0);
    cudaStreamWaitEvent(s1, ev_start, 0);

    // s0: fp16(x), then KV chain (rope+round fused into gemm epilogue)
    round_x_h<<<(NTOK * DM_ / 4 + 255) / 256, 256>>>(x, xh, NTOK * DM_ / 4);
    cudaEventRecord(ev_rx, 0);
    transpose_h_kernel<<<dim3(2048 / 32, DM_ / 32), dim3(32, 8)>>>(w_kv, wkvTh, DM_, 2048);
    gemm_tc<<<dim3(2048 / BN, NTOK / BM), 256, GEMM_SMEM>>>(
        xh, wkvTh, kvb, 2048, 2, rcos, rsin);

    // s1: Q chain (concurrent with KV chain) + w_o transpose
    transpose_h_kernel<<<dim3(DM_ / 32, DM_ / 32), dim3(32, 8), 0, s1>>>(w_q, wqTh, DM_, DM_);
    cudaStreamWaitEvent(s1, ev_rx, 0);
    gemm_tc<<<dim3(DM_ / BN, NTOK / BM), 256, GEMM_SMEM, s1>>>(
        xh, wqTh, qb, DM_, 1, rcos, rsin);
    cudaEventRecord(ev_q, s1);
    transpose_h_kernel<<<dim3(DM_ / 32, DM_ / 32), dim3(32, 8), 0, s1>>>(w_o, woTh, DM_, DM_);
    cudaEventRecord(ev_wo, s1);

    // s0: attention half 0 (batches 0,1), then half 1 (batches 2,3)
    cudaStreamWaitEvent(0, ev_q, 0);
    attn_kernel<<<dim3(T_ / 64, H_, 2), 128, ATT_SMEM_FLOATS * 4>>>(qb, kvb, ath, 0);
    cudaEventRecord(ev_a0, 0);
    attn_kernel<<<dim3(T_ / 64, H_, 2), 128, ATT_SMEM_FLOATS * 4>>>(qb, kvb, ath, 2);

    // s1: O-projection half 0 (rows 0..2047) overlapping attention half 1
    cudaStreamWaitEvent(s1, ev_a0, 0);
    cudaStreamWaitEvent(s1, ev_wo, 0);
    gemm_tc<<<dim3(DM_ / BN, (NTOK / 2) / BM), 256, GEMM_SMEM, s1>>>(
        ath, woTh, out, DM_, 0, rcos, rsin);
    cudaEventRecord(ev_o0, s1);

    // s0: O-projection half 1 (rows 2048..4095), then join
    cudaStreamWaitEvent(0, ev_wo, 0);
    gemm_tc<<<dim3(DM_ / BN, (NTOK / 2) / BM), 256, GEMM_SMEM>>>(
        ath + (size_t)(NTOK / 2) * DM_, woTh, out + (size_t)(NTOK / 2) * DM_,
        DM_, 0, rcos, rsin);
    cudaStreamWaitEvent(0, ev_o0, 0);
}

// round 14
// speedup vs baseline: 1.9606x; 1.2181x over previous
#include <cuda_runtime.h>
#include <cuda_fp16.h>
#include <cstdint>
#include <cstddef>

#define B_   4
#define T_   1024
#define H_   32
#define KVH_ 8
#define HD_  128
#define DM_  4096
#define NTOK (B_ * T_)
#define KDIM 4096

// ---------------------------------------------------------------------------
// Scratch (device globals — no runtime allocation allowed)
// ---------------------------------------------------------------------------
__device__ __half g_xh   [(size_t)NTOK * DM_];  // fp16(x)
__device__ __half g_wqTh [(size_t)DM_ * DM_];   // fp16(w_q)^T  [N][K]
__device__ __half g_wkvTh[(size_t)2048 * DM_];  // fp16(w_kv)^T [N][K]
__device__ __half g_woTh [(size_t)DM_ * DM_];   // fp16(w_o)^T  [N][K]
__device__ __half g_qh   [(size_t)NTOK * DM_];  // q after proj+rope (fp16)
__device__ __half g_kh   [(size_t)NTOK * 1024]; // k after proj+rope (fp16) [n][kvh*128+d]
__device__ __half g_vTh  [(size_t)B_ * KVH_ * HD_ * T_]; // V transposed [b][kvh][d][t]
__device__ __half g_atth [(size_t)NTOK * DM_];  // attention out (fp16)

// ---------------------------------------------------------------------------
// helpers
// ---------------------------------------------------------------------------
__device__ __forceinline__ uint32_t smem_u32(const void* p) {
    uint32_t a;
    asm("{ .reg .u64 t; cvta.to.shared.u64 t, %1; cvt.u32.u64 %0, t; }"
        : "=r"(a) : "l"(p));
    return a;
}

__device__ __forceinline__ void cp_async16(uint32_t dst, const void* src) {
    asm volatile("cp.async.cg.shared.global [%0], [%1], 16;\n"
                 :: "r"(dst), "l"(src) : "memory");
}
#define CP_COMMIT() asm volatile("cp.async.commit_group;\n" ::: "memory")
#define CP_WAIT(n)  asm volatile("cp.async.wait_group %0;\n" :: "n"(n) : "memory")

// fp16 mma m16n8k16, fp32 accum
__device__ __forceinline__ void mma_f16(float d[4], const uint32_t a[4],
                                        uint32_t b0, uint32_t b1) {
    asm volatile(
        "mma.sync.aligned.m16n8k16.row.col.f32.f16.f16.f32 "
        "{%0,%1,%2,%3}, {%4,%5,%6,%7}, {%8,%9}, {%0,%1,%2,%3};\n"
        : "+f"(d[0]), "+f"(d[1]), "+f"(d[2]), "+f"(d[3])
        : "r"(a[0]), "r"(a[1]), "r"(a[2]), "r"(a[3]), "r"(b0), "r"(b1));
}

__device__ __forceinline__ uint32_t pack_h2(float x, float y) {
    __half2 h = __floats2half2_rn(x, y);
    return *(uint32_t*)&h;
}

// ---------------------------------------------------------------------------
// fp16 GEMM: C = A[M,K] @ Bt[N,K]^T. Block 256x128, BK=64, 256 thr, 2-stage.
// Epilogue modes:
//   0: fp32 store                  (O-projection -> out)
//   1: rope + fp16 store           (Q-projection -> g_qh)
//   2: n0<1024: rope+fp16 -> g_kh; n0>=1024: fp16 transposed -> g_vTh
// ---------------------------------------------------------------------------
#define BM 256
#define BN 128
#define BK 64
#define HTS 72
#define A_TILE_B (BM * HTS * 2)
#define B_TILE_B (BN * HTS * 2)
#define STG_B (A_TILE_B + B_TILE_B)
#define GEMM_SMEM (2 * STG_B)

__global__ void __launch_bounds__(256, 1)
gemm_tc(const __half* __restrict__ A, const __half* __restrict__ Bt,
        void* __restrict__ Cv, int N, int mode,
        const float* __restrict__ rcos, const float* __restrict__ rsin,
        __half* __restrict__ vT) {
    extern __shared__ char smc[];
    const uint32_t sbase = smem_u32(smc);

    const int tid  = threadIdx.x;
    const int warp = tid >> 5;
    const int lane = tid & 31;
    const int wm = warp & 3;
    const int wn = warp >> 2;
    const int gr = lane >> 2;
    const int tg = lane & 3;
    const int m0 = blockIdx.y * BM;
    const int n0 = blockIdx.x * BN;
    const int NK = KDIM / BK;

    const __half* aseg = A  + (size_t)m0 * KDIM;
    const __half* bseg = Bt + (size_t)n0 * KDIM;

    auto load_stage = [&](int s, int kt) {
        const uint32_t dst = sbase + (uint32_t)s * STG_B;
        const int kf = kt * BK;
        #pragma unroll
        for (int p = 0; p < 8; p++) {
            int i = tid + p * 256;
            int row = i >> 3, u = i & 7;
            cp_async16(dst + (uint32_t)(row * 144 + u * 16),
                       aseg + (size_t)row * KDIM + kf + u * 8);
        }
        const uint32_t dstB = dst + (uint32_t)A_TILE_B;
        #pragma unroll
        for (int p = 0; p < 4; p++) {
            int i = tid + p * 256;
            int row = i >> 3, u = i & 7;
            cp_async16(dstB + (uint32_t)(row * 144 + u * 16),
                       bseg + (size_t)row * KDIM + kf + u * 8);
        }
        CP_COMMIT();
    };

    float acc[4][8][4];
    #pragma unroll
    for (int mt = 0; mt < 4; mt++)
        #pragma unroll
        for (int nt = 0; nt < 8; nt++)
            #pragma unroll
            for (int e = 0; e < 4; e++) acc[mt][nt][e] = 0.f;

    load_stage(0, 0);

    for (int kt = 0; kt < NK; kt++) {
        if (kt + 1 < NK) {
            load_stage((kt + 1) & 1, kt + 1);
            CP_WAIT(1);
        } else {
            CP_WAIT(0);
        }
        __syncthreads();

        const __half* As = (const __half*)(smc + (size_t)(kt & 1) * STG_B);
        const __half* Bs = (const __half*)((const char*)As + A_TILE_B);
        const __half* Aw = As + (wm * 64 + gr) * HTS;
        const __half* Bw = Bs + (wn * 64 + gr) * HTS;

        #pragma unroll
        for (int ks = 0; ks < 4; ks++) {
            const int c0 = ks * 16 + 2 * tg;
            uint32_t af[4][4];
            #pragma unroll
            for (int mt = 0; mt < 4; mt++) {
                const __half* ap = Aw + mt * 16 * HTS;
                af[mt][0] = *(const uint32_t*)(ap + c0);
                af[mt][1] = *(const uint32_t*)(ap + 8 * HTS + c0);
                af[mt][2] = *(const uint32_t*)(ap + c0 + 8);
                af[mt][3] = *(const uint32_t*)(ap + 8 * HTS + c0 + 8);
            }
            #pragma unroll
            for (int nt = 0; nt < 8; nt++) {
                const __half* bp = Bw + nt * 8 * HTS;
                uint32_t b0 = *(const uint32_t*)(bp + c0);
                uint32_t b1 = *(const uint32_t*)(bp + c0 + 8);
                #pragma unroll
                for (int mt = 0; mt < 4; mt++)
                    mma_f16(acc[mt][nt], af[mt], b0, b1);
            }
        }
        __syncthreads();
    }

    // ---- fused epilogue ----
    #pragma unroll
    for (int mt = 0; mt < 4; mt++) {
        #pragma unroll
        for (int e2 = 0; e2 < 2; e2++) {
            int row = m0 + wm * 64 + mt * 16 + gr + e2 * 8;
            if (mode == 0) {
                float* C = (float*)Cv;
                float* crow = C + (size_t)row * N + n0 + wn * 64;
                #pragma unroll
                for (int nt = 0; nt < 8; nt++) {
                    float2 v;
                    v.x = acc[mt][nt][e2 * 2];
                    v.y = acc[mt][nt][e2 * 2 + 1];
                    *(float2*)(crow + nt * 8 + 2 * tg) = v;
                }
            } else if (mode == 1) {
                __half* C = (__half*)Cv;
                int pos = row & (T_ - 1);
                #pragma unroll
                for (int nt = 0; nt < 8; nt++) {
                    float x1 = acc[mt][nt][e2 * 2];
                    float x2 = acc[mt][nt][e2 * 2 + 1];
                    int col = n0 + wn * 64 + nt * 8 + 2 * tg;
                    int i = (col & 127) >> 1;
                    float cs = __ldg(&rcos[pos * 64 + i]);
                    float sn = __ldg(&rsin[pos * 64 + i]);
                    *(uint32_t*)(C + (size_t)row * N + col) =
                        pack_h2(x1 * cs - x2 * sn, x1 * sn + x2 * cs);
                }
            } else if (n0 < 1024) {
                // K half: rope + fp16, row-stride 1024
                __half* kh = (__half*)Cv;
                int pos = row & (T_ - 1);
                #pragma unroll
                for (int nt = 0; nt < 8; nt++) {
                    float x1 = acc[mt][nt][e2 * 2];
                    float x2 = acc[mt][nt][e2 * 2 + 1];
                    int col = n0 + wn * 64 + nt * 8 + 2 * tg;
                    int i = (col & 127) >> 1;
                    float cs = __ldg(&rcos[pos * 64 + i]);
                    float sn = __ldg(&rsin[pos * 64 + i]);
                    *(uint32_t*)(kh + (size_t)row * 1024 + col) =
                        pack_h2(x1 * cs - x2 * sn, x1 * sn + x2 * cs);
                }
            } else {
                // V half: fp16, transposed [b][kvh][d][t]
                int t = row & (T_ - 1);
                int bb = row >> 10;
                #pragma unroll
                for (int nt = 0; nt < 8; nt++) {
                    int v_col = n0 - 1024 + wn * 64 + nt * 8 + 2 * tg;
                    int kvh = v_col >> 7, d = v_col & 127;
                    __half* vp = vT + ((size_t)(bb * KVH_ + kvh) * HD_ + d) * T_ + t;
                    vp[0]  = __float2half_rn(acc[mt][nt][e2 * 2]);
                    vp[T_] = __float2half_rn(acc[mt][nt][e2 * 2 + 1]);
                }
            }
        }
    }
}

// ---------------------------------------------------------------------------
// prep kernels: fp32 -> fp16
// ---------------------------------------------------------------------------
__global__ void round_x_h(const float* __restrict__ in, __half* __restrict__ out,
                          int n4) {
    int i = blockIdx.x * blockDim.x + threadIdx.x;
    if (i >= n4) return;
    float4 v = ((const float4*)in)[i];
    ((__half2*)out)[2 * i]     = __floats2half2_rn(v.x, v.y);
    ((__half2*)out)[2 * i + 1] = __floats2half2_rn(v.z, v.w);
}

__global__ void transpose_h_kernel(const float* __restrict__ W, __half* __restrict__ Wt,
                                   int rows /*K*/, int cols /*N*/) {
    __shared__ float t[32][33];
    int bx = blockIdx.x * 32;
    int by = blockIdx.y * 32;
    int lx = threadIdx.x, ly = threadIdx.y;   // 32 x 8
    #pragma unroll
    for (int i = 0; i < 32; i += 8)
        t[ly + i][lx] = W[(size_t)(by + ly + i) * cols + bx + lx];
    __syncthreads();
    #pragma unroll
    for (int i = 0; i < 32; i += 8)
        Wt[(size_t)(bx + ly + i) * rows + by + lx] = __float2half_rn(t[lx][ly + i]);
}

// ---------------------------------------------------------------------------
// Flash attention, causal, GQA, **fp16 mma** (m16n8k16), fp32 softmax.
// grid = (T/64, H, nb), block = 128 (4 warps). b = b_off + blockIdx.z.
// smem: Ks[64x136h] + Vs[128x72h, d-major] + Qs[64x136h] (Ps aliases Qs)
//       = 53248 B -> 4 CTAs/SM.
// ---------------------------------------------------------------------------
#define QTS 136
#define VTS 72
#define ATT_SMEM_BYTES (64 * QTS * 2 + 128 * VTS * 2 + 64 * QTS * 2)

__global__ void __launch_bounds__(128)
attn_kernel(const __half* __restrict__ qh, const __half* __restrict__ kh,
            const __half* __restrict__ vT, __half* __restrict__ out, int b_off) {
    extern __shared__ char smc[];
    __half* Ks = (__half*)smc;                    // 64 x 136
    __half* Vs = Ks + 64 * QTS;                   // 128 x 72 (d-major)
    __half* Qs = Vs + 128 * VTS;                  // 64 x 136
    __half* Ps = Qs;                              // alias (per-warp rows)
    const uint32_t sK = smem_u32(Ks);
    const uint32_t sV = smem_u32(Vs);
    const uint32_t sQ = smem_u32(Qs);

    const int mblk = gridDim.x - 1 - blockIdx.x;  // longest tiles first
    const int m0  = mblk * 64;
    const int h   = blockIdx.y;
    const int b   = b_off + blockIdx.z;
    const int kvh = h >> 2;
    const int tid  = threadIdx.x;
    const int warp = tid >> 5;
    const int lane = tid & 31;
    const int gr = lane >> 2;
    const int tg = lane & 3;

    // load Q tile (fp16): 1024 x 16B chunks
    #pragma unroll
    for (int p = 0; p < 8; p++) {
        int i = tid + p * 128;
        int r = i >> 4, c = i & 15;
        cp_async16(sQ + (uint32_t)(r * QTS + c * 8) * 2u,
                   qh + (size_t)(b * T_ + m0 + r) * DM_ + h * HD_ + c * 8);
    }
    CP_COMMIT();
    CP_WAIT(0);
    __syncthreads();

    // Q fragments: 8 k16 steps
    uint32_t qf[8][4];
    #pragma unroll
    for (int ks = 0; ks < 8; ks++) {
        int r0 = warp * 16 + gr;
        int c0 = ks * 16 + 2 * tg;
        qf[ks][0] = *(const uint32_t*)(Qs + r0 * QTS + c0);
        qf[ks][1] = *(const uint32_t*)(Qs + (r0 + 8) * QTS + c0);
        qf[ks][2] = *(const uint32_t*)(Qs + r0 * QTS + c0 + 8);
        qf[ks][3] = *(const uint32_t*)(Qs + (r0 + 8) * QTS + c0 + 8);
    }

    float o_acc[16][4];
    #pragma unroll
    for (int nt = 0; nt < 16; nt++)
        #pragma unroll
        for (int e = 0; e < 4; e++) o_acc[nt][e] = 0.f;
    float m_i[2] = {-INFINITY, -INFINITY};
    float l_i[2] = {0.f, 0.f};

    const float scale = 0.08838834764831845f;
    const int ktiles = m0 / 64 + 1;

    for (int kt = 0; kt < ktiles; kt++) {
        int k0 = kt * 64;
        __syncthreads();
        {
            // K tile: 64 rows x 128 d
            #pragma unroll
            for (int p = 0; p < 8; p++) {
                int i = tid + p * 128;
                int r = i >> 4, c = i & 15;
                cp_async16(sK + (uint32_t)(r * QTS + c * 8) * 2u,
                           kh + (size_t)(b * T_ + k0 + r) * 1024 + kvh * 128 + c * 8);
            }
            // V tile (d-major): 128 d rows x 64 keys
            #pragma unroll
            for (int p = 0; p < 8; p++) {
                int i = tid + p * 128;
                int d = i >> 3, c = i & 7;
                cp_async16(sV + (uint32_t)(d * VTS + c * 8) * 2u,
                           vT + ((size_t)(b * KVH_ + kvh) * HD_ + d) * T_ + k0 + c * 8);
            }
            CP_COMMIT();
            CP_WAIT(0);
        }
        __syncthreads();

        float s[8][4];
        #pragma unroll
        for (int nt = 0; nt < 8; nt++)
            #pragma unroll
            for (int e = 0; e < 4; e++) s[nt][e] = 0.f;

        #pragma unroll
        for (int ks = 0; ks < 8; ks++) {
            const int c0 = ks * 16 + 2 * tg;
            #pragma unroll
            for (int nt = 0; nt < 8; nt++) {
                const __half* kp = Ks + (nt * 8 + gr) * QTS;
                uint32_t b0 = *(const uint32_t*)(kp + c0);
                uint32_t b1 = *(const uint32_t*)(kp + c0 + 8);
                mma_f16(s[nt], qf[ks], b0, b1);
            }
        }

        bool diag = (kt == ktiles - 1);
        #pragma unroll
        for (int nt = 0; nt < 8; nt++)
            #pragma unroll
            for (int e = 0; e < 4; e++) {
                int row = warp * 16 + gr + ((e >= 2) ? 8 : 0);
                int col = nt * 8 + 2 * tg + (e & 1);
                float v = s[nt][e] * scale;
                if (diag && (k0 + col > m0 + row)) v = -1e9f;
                s[nt][e] = v;
            }

        #pragma unroll
        for (int half = 0; half < 2; half++) {
            float mx = -INFINITY;
            #pragma unroll
            for (int nt = 0; nt < 8; nt++) {
                mx = fmaxf(mx, s[nt][half * 2]);
                mx = fmaxf(mx, s[nt][half * 2 + 1]);
            }
            mx = fmaxf(mx, __shfl_xor_sync(0xffffffffu, mx, 1));
            mx = fmaxf(mx, __shfl_xor_sync(0xffffffffu, mx, 2));
            float mnew = fmaxf(m_i[half], mx);
            float corr = __expf(m_i[half] - mnew);
            float lsum = 0.f;
            #pragma unroll
            for (int nt = 0; nt < 8; nt++) {
                float e0 = __expf(s[nt][half * 2]     - mnew);
                float e1 = __expf(s[nt][half * 2 + 1] - mnew);
                s[nt][half * 2]     = e0;
                s[nt][half * 2 + 1] = e1;
                lsum += e0 + e1;
            }
            lsum += __shfl_xor_sync(0xffffffffu, lsum, 1);
            lsum += __shfl_xor_sync(0xffffffffu, lsum, 2);
            m_i[half] = mnew;
            l_i[half] = l_i[half] * corr + lsum;
            #pragma unroll
            for (int nt = 0; nt < 16; nt++) {
                o_acc[nt][half * 2]     *= corr;
                o_acc[nt][half * 2 + 1] *= corr;
            }
        }

        // P -> Ps as fp16 pairs (per-warp rows; half2 stores)
        #pragma unroll
        for (int nt = 0; nt < 8; nt++)
            #pragma unroll
            for (int e2 = 0; e2 < 2; e2++) {
                int row = warp * 16 + gr + e2 * 8;
                *(uint32_t*)(Ps + row * VTS + nt * 8 + 2 * tg) =
                    pack_h2(s[nt][e2 * 2], s[nt][e2 * 2 + 1]);
            }
        __syncwarp();

        // O += P @ V : 4 k16 steps over 64 keys
        #pragma unroll
        for (int ks = 0; ks < 4; ks++) {
            const int c0 = ks * 16 + 2 * tg;
            uint32_t pa[4];
            int r0 = warp * 16 + gr;
            pa[0] = *(const uint32_t*)(Ps + r0 * VTS + c0);
            pa[1] = *(const uint32_t*)(Ps + (r0 + 8) * VTS + c0);
            pa[2] = *(const uint32_t*)(Ps + r0 * VTS + c0 + 8);
            pa[3] = *(const uint32_t*)(Ps + (r0 + 8) * VTS + c0 + 8);
            #pragma unroll
            for (int nt = 0; nt < 16; nt++) {
                const __half* vp = Vs + (nt * 8 + gr) * VTS;
                uint32_t b0 = *(const uint32_t*)(vp + c0);
                uint32_t b1 = *(const uint32_t*)(vp + c0 + 8);
                mma_f16(o_acc[nt], pa, b0, b1);
            }
        }
    }

    // epilogue: fp16 store (feeds fp16 O-projection)
    #pragma unroll
    for (int nt = 0; nt < 16; nt++)
        #pragma unroll
        for (int e2 = 0; e2 < 2; e2++) {
            int row = warp * 16 + gr + e2 * 8;
            float inv_l = 1.f / l_i[e2];
            int col = nt * 8 + 2 * tg;
            *(uint32_t*)(out + (size_t)(b * T_ + m0 + row) * DM_ + h * HD_ + col) =
                pack_h2(o_acc[nt][e2 * 2] * inv_l, o_acc[nt][e2 * 2 + 1] * inv_l);
        }
}

// ---------------------------------------------------------------------------
// launch — fork (Q chain ∥ KV chain), then attn/O-GEMM split pipeline
// ---------------------------------------------------------------------------
extern "C" void kernel_launch(void* const* d_in, const int* in_sizes, int n_in,
                              void* d_out, int out_size) {
    const float* x    = (const float*)d_in[0];
    const float* w_q  = (const float*)d_in[1];
    const float* w_kv = (const float*)d_in[2];
    const float* w_o  = (const float*)d_in[3];
    const float* rcos = (const float*)d_in[6];
    const float* rsin = (const float*)d_in[7];
    float* out = (float*)d_out;

    __half *xh, *wqTh, *wkvTh, *woTh, *qh, *kh, *vTh, *ath;
    cudaGetSymbolAddress((void**)&xh,    g_xh);
    cudaGetSymbolAddress((void**)&wqTh,  g_wqTh);
    cudaGetSymbolAddress((void**)&wkvTh, g_wkvTh);
    cudaGetSymbolAddress((void**)&woTh,  g_woTh);
    cudaGetSymbolAddress((void**)&qh,    g_qh);
    cudaGetSymbolAddress((void**)&kh,    g_kh);
    cudaGetSymbolAddress((void**)&vTh,   g_vTh);
    cudaGetSymbolAddress((void**)&ath,   g_atth);

    static cudaStream_t s1 = nullptr;
    static cudaEvent_t ev_start = nullptr, ev_rx = nullptr, ev_q = nullptr,
                       ev_wo = nullptr, ev_a0 = nullptr, ev_o0 = nullptr;
    if (s1 == nullptr) {
        cudaStreamCreateWithFlags(&s1, cudaStreamNonBlocking);
        cudaEventCreateWithFlags(&ev_start, cudaEventDisableTiming);
        cudaEventCreateWithFlags(&ev_rx,    cudaEventDisableTiming);
        cudaEventCreateWithFlags(&ev_q,     cudaEventDisableTiming);
        cudaEventCreateWithFlags(&ev_wo,    cudaEventDisableTiming);
        cudaEventCreateWithFlags(&ev_a0,    cudaEventDisableTiming);
        cudaEventCreateWithFlags(&ev_o0,    cudaEventDisableTiming);
        cudaFuncSetAttribute(gemm_tc,
            cudaFuncAttributeMaxDynamicSharedMemorySize, GEMM_SMEM);
        cudaFuncSetAttribute(attn_kernel,
            cudaFuncAttributeMaxDynamicSharedMemorySize, ATT_SMEM_BYTES);
    }

    // fork
    cudaEventRecord(ev_start, 0);
    cudaStreamWaitEvent(s1, ev_start, 0);

    // s0: fp16(x), then KV chain (rope/transpose fused in gemm epilogue)
    round_x_h<<<(NTOK * DM_ / 4 + 255) / 256, 256>>>(x, xh, NTOK * DM_ / 4);
    cudaEventRecord(ev_rx, 0);
    transpose_h_kernel<<<dim3(2048 / 32, DM_ / 32), dim3(32, 8)>>>(w_kv, wkvTh, DM_, 2048);
    gemm_tc<<<dim3(2048 / BN, NTOK / BM), 256, GEMM_SMEM>>>(
        xh, wkvTh, kh, 2048, 2, rcos, rsin, vTh);

    // s1: Q chain (concurrent with KV chain) + w_o transpose
    transpose_h_kernel<<<dim3(DM_ / 32, DM_ / 32), dim3(32, 8), 0, s1>>>(w_q, wqTh, DM_, DM_);
    cudaStreamWaitEvent(s1, ev_rx, 0);
    gemm_tc<<<dim3(DM_ / BN, NTOK / BM), 256, GEMM_SMEM, s1>>>(
        xh, wqTh, qh, DM_, 1, rcos, rsin, nullptr);
    cudaEventRecord(ev_q, s1);
    transpose_h_kernel<<<dim3(DM_ / 32, DM_ / 32), dim3(32, 8), 0, s1>>>(w_o, woTh, DM_, DM_);
    cudaEventRecord(ev_wo, s1);

    // s0: attention half 0 (batches 0,1), then half 1 (batches 2,3)
    cudaStreamWaitEvent(0, ev_q, 0);
    attn_kernel<<<dim3(T_ / 64, H_, 2), 128, ATT_SMEM_BYTES>>>(qh, kh, vTh, ath, 0);
    cudaEventRecord(ev_a0, 0);
    attn_kernel<<<dim3(T_ / 64, H_, 2), 128, ATT_SMEM_BYTES>>>(qh, kh, vTh, ath, 2);

    // s1: O-projection half 0 (rows 0..2047) overlapping attention half 1
    cudaStreamWaitEvent(s1, ev_a0, 0);
    cudaStreamWaitEvent(s1, ev_wo, 0);
    gemm_tc<<<dim3(DM_ / BN, (NTOK / 2) / BM), 256, GEMM_SMEM, s1>>>(
        ath, woTh, out, DM_, 0, rcos, rsin, nullptr);
    cudaEventRecord(ev_o0, s1);

    // s0: O-projection half 1 (rows 2048..4095), then join
    cudaStreamWaitEvent(0, ev_wo, 0);
    gemm_tc<<<dim3(DM_ / BN, (NTOK / 2) / BM), 256, GEMM_SMEM>>>(
        ath + (size_t)(NTOK / 2) * DM_, woTh, out + (size_t)(NTOK / 2) * DM_,
        DM_, 0, rcos, rsin, nullptr);
    cudaStreamWaitEvent(0, ev_o0, 0);
}